// round 13
// baseline (speedup 1.0000x reference)
#include <cuda_runtime.h>
#include <cuda_fp16.h>
#include <cstdint>

// ============================================================================
// out[z,k] = sum_{i,j} M[k,i,j] * f1[z,i] * f2[z,j]
// Dense fp16 warp-MMA GEMM (fp32 accum):  out = P @ W
//   P[z, i*32+j] = f1[z,i]*f2[z,j]  (HMUL2 of pre-converted fp16 operands)
//   W[i*32+j, k] = M[k,i,j]         (pre-packed fp16x2 fragment order, RN)
//
// R13 = R12 with the chunk-advance bug fixed: B is loaded PER k16 chunk
//   (inside the jh loop). No deep prefetch (reg budget); loads sit ~25
//   issue-slots ahead of first consumer, L1-broadcast across all 8 warps.
//   Warp tile m32 x n64, 256 thr x 2 CTA/SM, Z_CTA=256, grid 512.
// ============================================================================

#define N_I 32
#define N_J 32
#define N_K 64
#define Z_CTA 256              // 8 m-groups x 32 rows
#define NTHREADS 256           // 8 warps, each = one m-group, full n64
#define N_CHUNKS 64            // K = 1024 / 16

// Packed W (uint32 = fp16x2), layout identical to R7/R8 (validated):
//   uint4 index = chunk*128 + g*32 + lane,  g = 0..3 (n-tile pair)
//   slot (u32 within uint4) = ntl*2 + breg ; ntile = g*2 + ntl ; n = ntile*8+qr
//   i = chunk/2 ; j0 = (chunk&1)*16 + 2c + 8*breg
//   value = {f16rn(M[n,i,j0]), f16rn(M[n,i,j0+1])}
__device__ uint32_t g_Wp[N_CHUNKS * 512];   // 128 KB

// ---------------------------------------------------------------------------
__global__ void etp_pack_kernel(const float* __restrict__ Mx) {
    int idx = blockIdx.x * blockDim.x + threadIdx.x;   // 0..32767
    if (idx >= N_CHUNKS * 512) return;
    int chunk = idx >> 9;
    int rem   = idx & 511;
    int g     = rem >> 7;          // n-tile pair 0..3
    int r3    = rem & 127;
    int lane  = r3 >> 2;
    int slot  = r3 & 3;
    int ntl   = slot >> 1;
    int breg  = slot & 1;
    int qr    = lane >> 2;
    int c     = lane & 3;
    int n     = (g * 2 + ntl) * 8 + qr;
    int i     = chunk >> 1;
    int j0    = ((chunk & 1) << 4) + 2 * c + 8 * breg;
    float v0 = Mx[n * (N_I * N_J) + i * N_J + j0];
    float v1 = Mx[n * (N_I * N_J) + i * N_J + j0 + 1];
    __half2 h = __floats2half2_rn(v0, v1);             // lo=v0, hi=v1
    g_Wp[idx] = *reinterpret_cast<uint32_t*>(&h);
}

// ---------------------------------------------------------------------------

#define HMUL2(d, x, y) \
    asm("mul.rn.f16x2 %0, %1, %2;" : "=r"(d) : "r"(x), "r"(y))

#define MMA_F16(cacc, a0, a1, a2, a3, b0, b1)                                 \
    asm volatile(                                                             \
        "mma.sync.aligned.m16n8k16.row.col.f32.f16.f16.f32 "                  \
        "{%0,%1,%2,%3}, {%4,%5,%6,%7}, {%8,%9}, {%0,%1,%2,%3};"               \
        : "+f"((cacc)[0]), "+f"((cacc)[1]), "+f"((cacc)[2]), "+f"((cacc)[3])  \
        : "r"(a0), "r"(a1), "r"(a2), "r"(a3), "r"(b0), "r"(b1))

__global__ void __launch_bounds__(NTHREADS, 2)
etp_mma_kernel(const float* __restrict__ F1,
               const float* __restrict__ F2,
               float* __restrict__ Out) {
    // f1 broadcast half2(v,v), stride 32, XOR-swizzled:
    //   word = row*32 + (col ^ ((row&7)<<2))
    __shared__ uint32_t f1h[Z_CTA * 32];                 // 32 KB

    const int tid  = threadIdx.x;
    const int warp = tid >> 5;           // m-group 0..7 (32 rows each)
    const int lane = tid & 31;
    const int qr   = lane >> 2;          // 0..7
    const int c    = lane & 3;           // 0..3

    const size_t zbase = (size_t)blockIdx.x * Z_CTA;

    // ---- stage f1 (broadcast half2, swizzled): 2048 float4, 8 per thread ----
    {
        const float4* f1g = reinterpret_cast<const float4*>(F1 + zbase * N_I);
#pragma unroll
        for (int t = 0; t < 8; t++) {
            int i4 = tid + t * NTHREADS;          // 0..2047
            int row = i4 >> 3, cg = i4 & 7;
            float4 v1 = __ldg(f1g + i4);
            __half2 h0 = __half2half2(__float2half_rn(v1.x));
            __half2 h1 = __half2half2(__float2half_rn(v1.y));
            __half2 h2 = __half2half2(__float2half_rn(v1.z));
            __half2 h3 = __half2half2(__float2half_rn(v1.w));
            uint4 pk;
            pk.x = *reinterpret_cast<uint32_t*>(&h0);
            pk.y = *reinterpret_cast<uint32_t*>(&h1);
            pk.z = *reinterpret_cast<uint32_t*>(&h2);
            pk.w = *reinterpret_cast<uint32_t*>(&h3);
            int col = (cg * 4) ^ ((row & 7) << 2);       // keeps low 2 bits
            *reinterpret_cast<uint4*>(&f1h[row * 32 + col]) = pk;
        }
    }

    const int r0 = warp * 32 + qr;       // rows r0, r0+8, r0+16, r0+24

    // ---- f2 pair regs direct from gmem: s2 = jh*2+breg -> j0 = jh*16+breg*8+2c
    uint32_t f2h[4][4];
#pragma unroll
    for (int rr = 0; rr < 4; rr++) {
        const float* fr = F2 + (zbase + r0 + rr * 8) * N_J;
#pragma unroll
        for (int s2 = 0; s2 < 4; s2++) {
            int jh = s2 >> 1, breg = s2 & 1;
            int j0 = jh * 16 + breg * 8 + 2 * c;
            float2 v = *reinterpret_cast<const float2*>(fr + j0);
            __half2 h = __floats2half2_rn(v.x, v.y);
            f2h[rr][s2] = *reinterpret_cast<uint32_t*>(&h);
        }
    }

    float C[2][8][4];                    // [mtile][ntile][quad] = 64 regs
#pragma unroll
    for (int mt = 0; mt < 2; mt++)
#pragma unroll
        for (int nt = 0; nt < 8; nt++)
#pragma unroll
            for (int q = 0; q < 4; q++) C[mt][nt][q] = 0.0f;

    __syncthreads();                     // f1h visible

    const int sw = qr << 2;              // f1 swizzle term (row&7 == qr)

    // ---- B stream: 4 lane-contiguous LDG.128 per k16 chunk ----
    const uint4* wq = reinterpret_cast<const uint4*>(g_Wp) + lane;

#pragma unroll 1
    for (int ig = 0; ig < N_I; ig++) {
        uint32_t f1v[4];
#pragma unroll
        for (int rr = 0; rr < 4; rr++)
            f1v[rr] = f1h[(r0 + rr * 8) * 32 + (ig ^ sw)];

#pragma unroll
        for (int jh = 0; jh < 2; jh++) {
            // chunk = ig*2 + jh ; issue loads first (consumers ~25 slots away)
            const uint4 c0 = __ldg(wq);
            const uint4 c1 = __ldg(wq + 32);
            const uint4 c2 = __ldg(wq + 64);
            const uint4 c3 = __ldg(wq + 96);
            wq += 128;

            // A fragments: one HMUL2 each
            uint32_t a[2][4];
#pragma unroll
            for (int mt = 0; mt < 2; mt++) {
                HMUL2(a[mt][0], f1v[2 * mt],     f2h[2 * mt][jh * 2 + 0]);
                HMUL2(a[mt][1], f1v[2 * mt + 1], f2h[2 * mt + 1][jh * 2 + 0]);
                HMUL2(a[mt][2], f1v[2 * mt],     f2h[2 * mt][jh * 2 + 1]);
                HMUL2(a[mt][3], f1v[2 * mt + 1], f2h[2 * mt + 1][jh * 2 + 1]);
            }

            // 16 MMAs per chunk (2 mtiles x 8 ntiles), K=16 each
#pragma unroll
            for (int mt = 0; mt < 2; mt++) {
                MMA_F16(C[mt][0], a[mt][0], a[mt][1], a[mt][2], a[mt][3], c0.x, c0.y);
                MMA_F16(C[mt][1], a[mt][0], a[mt][1], a[mt][2], a[mt][3], c0.z, c0.w);
                MMA_F16(C[mt][2], a[mt][0], a[mt][1], a[mt][2], a[mt][3], c1.x, c1.y);
                MMA_F16(C[mt][3], a[mt][0], a[mt][1], a[mt][2], a[mt][3], c1.z, c1.w);
                MMA_F16(C[mt][4], a[mt][0], a[mt][1], a[mt][2], a[mt][3], c2.x, c2.y);
                MMA_F16(C[mt][5], a[mt][0], a[mt][1], a[mt][2], a[mt][3], c2.z, c2.w);
                MMA_F16(C[mt][6], a[mt][0], a[mt][1], a[mt][2], a[mt][3], c3.x, c3.y);
                MMA_F16(C[mt][7], a[mt][0], a[mt][1], a[mt][2], a[mt][3], c3.z, c3.w);
            }
        }
    }

    // ---- epilogue ----
#pragma unroll
    for (int mt = 0; mt < 2; mt++) {
        const size_t z0 = zbase + r0 + mt * 16;
        const size_t z1 = z0 + 8;
#pragma unroll
        for (int nt = 0; nt < 8; nt++) {
            const int col = nt * 8 + 2 * c;
            *reinterpret_cast<float2*>(Out + z0 * N_K + col) =
                make_float2(C[mt][nt][0], C[mt][nt][1]);
            *reinterpret_cast<float2*>(Out + z1 * N_K + col) =
                make_float2(C[mt][nt][2], C[mt][nt][3]);
        }
    }
}

// ---------------------------------------------------------------------------

extern "C" void kernel_launch(void* const* d_in, const int* in_sizes, int n_in,
                              void* d_out, int out_size) {
    const float* f1 = (const float*)d_in[0];   // [Z, 32]
    const float* f2 = (const float*)d_in[1];   // [Z, 32]
    const float* mx = (const float*)d_in[2];   // [64, 32, 32]
    float* out = (float*)d_out;                // [Z, 64]

    const int z_total = in_sizes[0] / N_I;     // 131072
    const int blocks = z_total / Z_CTA;        // 512

    etp_pack_kernel<<<128, 256>>>(mx);         // 128*256 = 32768
    etp_mma_kernel<<<blocks, NTHREADS>>>(f1, f2, out);
}

// round 14
// speedup vs baseline: 1.4932x; 1.4932x over previous
#include <cuda_runtime.h>
#include <cuda_fp16.h>
#include <cstdint>

// ============================================================================
// out[z,k] = sum_{i,j} M[k,i,j] * f1[z,i] * f2[z,j]
// Dense fp16 warp-MMA GEMM (fp32 accum):  out = P @ W
//   P[z, i*32+j] = f1[z,i]*f2[z,j]  (HMUL2 of pre-converted fp16 operands)
//   W[i*32+j, k] = M[k,i,j]         (pre-packed fp16x2 fragment order, RN)
//
// R14 = R8 (m32n32 warp tile, 256thr) software-pipelined one chunk ahead:
//   at chunk t: load B(t+1) + f1(t+1), compute a(t+1) HMUL2s, then issue
//   the 8 MMAs of chunk t whose operands were produced LAST iteration ->
//   dependency-free MMA bursts (fixes tensor-pipe starvation).
//   Ping-pong regs cost ~24 -> launch_bounds(256,2), 16 warps/SM.
// ============================================================================

#define N_I 32
#define N_J 32
#define N_K 64
#define Z_CTA 128              // 4 m-groups x 32 rows
#define NTHREADS 256           // 8 warps = 4 m-groups x 2 n-halves
#define N_CHUNKS 64            // K = 1024 / 16

// Packed W (uint32 = fp16x2), layout validated in R7/R8:
//   uint4 index = chunk*128 + nhalf*64 + pair*32 + lane
//   slot = ntl*2 + breg ; n = nhalf*32 + (pair*2+ntl)*8 + qr
//   i = chunk/2 ; j0 = (chunk&1)*16 + 2c + 8*breg ; value = {f16(j0), f16(j0+1)}
// +1 zero pad chunk so the t=63 prefetch is legal.
__device__ uint32_t g_Wp[(N_CHUNKS + 1) * 512];   // 133 KB

// ---------------------------------------------------------------------------
__global__ void etp_pack_kernel(const float* __restrict__ Mx) {
    int idx = blockIdx.x * blockDim.x + threadIdx.x;   // 0..33279
    if (idx >= N_CHUNKS * 512) {
        if (idx < (N_CHUNKS + 1) * 512) g_Wp[idx] = 0u;
        return;
    }
    int chunk = idx >> 9;
    int rem   = idx & 511;
    int nhalf = rem >> 8;
    int r2    = rem & 255;
    int pair  = r2 >> 7;
    int r3    = r2 & 127;
    int lane  = r3 >> 2;
    int slot  = r3 & 3;
    int ntl   = slot >> 1;
    int breg  = slot & 1;
    int qr    = lane >> 2;
    int c     = lane & 3;
    int n     = nhalf * 32 + (pair * 2 + ntl) * 8 + qr;
    int i     = chunk >> 1;
    int j0    = ((chunk & 1) << 4) + 2 * c + 8 * breg;
    float v0 = Mx[n * (N_I * N_J) + i * N_J + j0];
    float v1 = Mx[n * (N_I * N_J) + i * N_J + j0 + 1];
    __half2 h = __floats2half2_rn(v0, v1);             // lo=v0, hi=v1
    g_Wp[idx] = *reinterpret_cast<uint32_t*>(&h);
}

// ---------------------------------------------------------------------------

#define HMUL2(d, x, y) \
    asm("mul.rn.f16x2 %0, %1, %2;" : "=r"(d) : "r"(x), "r"(y))

#define MMA_F16(cacc, a0, a1, a2, a3, b0, b1)                                 \
    asm volatile(                                                             \
        "mma.sync.aligned.m16n8k16.row.col.f32.f16.f16.f32 "                  \
        "{%0,%1,%2,%3}, {%4,%5,%6,%7}, {%8,%9}, {%0,%1,%2,%3};"               \
        : "+f"((cacc)[0]), "+f"((cacc)[1]), "+f"((cacc)[2]), "+f"((cacc)[3])  \
        : "r"(a0), "r"(a1), "r"(a2), "r"(a3), "r"(b0), "r"(b1))

__global__ void __launch_bounds__(NTHREADS, 2)
etp_mma_kernel(const float* __restrict__ F1,
               const float* __restrict__ F2,
               float* __restrict__ Out) {
    // f1 broadcast half2(v,v), stride 32, XOR-swizzled:
    //   word = row*32 + (col ^ ((row&7)<<2))
    // +64 words pad: the ig=32 prefetch (never consumed) stays in-bounds.
    __shared__ uint32_t f1h[Z_CTA * 32 + 64];            // ~16.25 KB

    const int tid    = threadIdx.x;
    const int warp   = tid >> 5;
    const int lane   = tid & 31;
    const int mgroup = warp >> 1;        // 0..3, 32 rows each
    const int nhalf  = warp & 1;         // n columns [nhalf*32, +32)
    const int qr     = lane >> 2;        // 0..7
    const int c      = lane & 3;         // 0..3

    const size_t zbase = (size_t)blockIdx.x * Z_CTA;

    // ---- stage f1 (broadcast half2, swizzled) ----
    {
        const float4* f1g = reinterpret_cast<const float4*>(F1 + zbase * N_I);
#pragma unroll
        for (int t = 0; t < 4; t++) {
            int i4 = tid + t * NTHREADS;          // 0..1023
            int row = i4 >> 3, cg = i4 & 7;
            float4 v1 = __ldg(f1g + i4);
            __half2 h0 = __half2half2(__float2half_rn(v1.x));
            __half2 h1 = __half2half2(__float2half_rn(v1.y));
            __half2 h2 = __half2half2(__float2half_rn(v1.z));
            __half2 h3 = __half2half2(__float2half_rn(v1.w));
            uint4 pk;
            pk.x = *reinterpret_cast<uint32_t*>(&h0);
            pk.y = *reinterpret_cast<uint32_t*>(&h1);
            pk.z = *reinterpret_cast<uint32_t*>(&h2);
            pk.w = *reinterpret_cast<uint32_t*>(&h3);
            int col = (cg * 4) ^ ((row & 7) << 2);       // keeps low 2 bits
            *reinterpret_cast<uint4*>(&f1h[row * 32 + col]) = pk;
        }
    }

    const int r0 = mgroup * 32 + qr;     // rows r0, r0+8, r0+16, r0+24

    // ---- f2 pair regs direct from gmem: s2 = jh*2+breg -> j0 = jh*16+breg*8+2c
    uint32_t f2h[4][4];
#pragma unroll
    for (int rr = 0; rr < 4; rr++) {
        const float* fr = F2 + (zbase + r0 + rr * 8) * N_J;
#pragma unroll
        for (int s2 = 0; s2 < 4; s2++) {
            int jh = s2 >> 1, breg = s2 & 1;
            int j0 = jh * 16 + breg * 8 + 2 * c;
            float2 v = *reinterpret_cast<const float2*>(fr + j0);
            __half2 h = __floats2half2_rn(v.x, v.y);
            f2h[rr][s2] = *reinterpret_cast<uint32_t*>(&h);
        }
    }

    float C[2][4][4];                    // [mtile][ntile][quad]
#pragma unroll
    for (int mt = 0; mt < 2; mt++)
#pragma unroll
        for (int nt = 0; nt < 4; nt++)
#pragma unroll
            for (int q = 0; q < 4; q++) C[mt][nt][q] = 0.0f;

    __syncthreads();                     // f1h visible

    const int sw = qr << 2;              // f1 swizzle term (row&7 == qr)

    // ---- pipelined state ----
    const uint4* wq = reinterpret_cast<const uint4*>(g_Wp)
                      + nhalf * 64 + lane;
    uint4    bbuf[2][2];                 // [parity][pair]
    uint32_t abuf[2][8];                 // [parity][frag]
    uint32_t f1v[4];

    // prolog: chunk 0 operands
    bbuf[0][0] = __ldg(wq);
    bbuf[0][1] = __ldg(wq + 32);
    wq += 128;
#pragma unroll
    for (int rr = 0; rr < 4; rr++)
        f1v[rr] = f1h[(r0 + rr * 8) * 32 + (0 ^ sw)];
    {
        HMUL2(abuf[0][0], f1v[0], f2h[0][0]);
        HMUL2(abuf[0][1], f1v[1], f2h[1][0]);
        HMUL2(abuf[0][2], f1v[0], f2h[0][1]);
        HMUL2(abuf[0][3], f1v[1], f2h[1][1]);
        HMUL2(abuf[0][4], f1v[2], f2h[2][0]);
        HMUL2(abuf[0][5], f1v[3], f2h[3][0]);
        HMUL2(abuf[0][6], f1v[2], f2h[2][1]);
        HMUL2(abuf[0][7], f1v[3], f2h[3][1]);
    }

#pragma unroll 2
    for (int t = 0; t < N_CHUNKS; t++) {
        const int ct = t & 1;
        const int nt = ct ^ 1;
        const int jh2 = (t + 1) & 1;     // jh of chunk t+1 (static under unroll 2)

        // ---- prepare chunk t+1 ----
        bbuf[nt][0] = __ldg(wq);         // pad chunk keeps t=63 legal
        bbuf[nt][1] = __ldg(wq + 32);
        wq += 128;

        if (jh2 == 0) {                  // crossing into next ig
            const int ig2 = (t + 1) >> 1;
#pragma unroll
            for (int rr = 0; rr < 4; rr++)
                f1v[rr] = f1h[(r0 + rr * 8) * 32 + (ig2 ^ sw)];
        }
        HMUL2(abuf[nt][0], f1v[0], f2h[0][jh2 * 2 + 0]);
        HMUL2(abuf[nt][1], f1v[1], f2h[1][jh2 * 2 + 0]);
        HMUL2(abuf[nt][2], f1v[0], f2h[0][jh2 * 2 + 1]);
        HMUL2(abuf[nt][3], f1v[1], f2h[1][jh2 * 2 + 1]);
        HMUL2(abuf[nt][4], f1v[2], f2h[2][jh2 * 2 + 0]);
        HMUL2(abuf[nt][5], f1v[3], f2h[3][jh2 * 2 + 0]);
        HMUL2(abuf[nt][6], f1v[2], f2h[2][jh2 * 2 + 1]);
        HMUL2(abuf[nt][7], f1v[3], f2h[3][jh2 * 2 + 1]);

        // ---- issue chunk t: operands fully ready since last iteration ----
        const uint4 b0 = bbuf[ct][0];
        const uint4 b1 = bbuf[ct][1];
        const uint32_t* a0 = &abuf[ct][0];   // mtile0
        const uint32_t* a1 = &abuf[ct][4];   // mtile1

        MMA_F16(C[0][0], a0[0], a0[1], a0[2], a0[3], b0.x, b0.y);
        MMA_F16(C[0][1], a0[0], a0[1], a0[2], a0[3], b0.z, b0.w);
        MMA_F16(C[0][2], a0[0], a0[1], a0[2], a0[3], b1.x, b1.y);
        MMA_F16(C[0][3], a0[0], a0[1], a0[2], a0[3], b1.z, b1.w);
        MMA_F16(C[1][0], a1[0], a1[1], a1[2], a1[3], b0.x, b0.y);
        MMA_F16(C[1][1], a1[0], a1[1], a1[2], a1[3], b0.z, b0.w);
        MMA_F16(C[1][2], a1[0], a1[1], a1[2], a1[3], b1.x, b1.y);
        MMA_F16(C[1][3], a1[0], a1[1], a1[2], a1[3], b1.z, b1.w);
    }

    // ---- epilogue ----
#pragma unroll
    for (int mt = 0; mt < 2; mt++) {
        const size_t z0 = zbase + r0 + mt * 16;
        const size_t z1 = z0 + 8;
#pragma unroll
        for (int nt = 0; nt < 4; nt++) {
            const int col = nhalf * 32 + nt * 8 + 2 * c;
            *reinterpret_cast<float2*>(Out + z0 * N_K + col) =
                make_float2(C[mt][nt][0], C[mt][nt][1]);
            *reinterpret_cast<float2*>(Out + z1 * N_K + col) =
                make_float2(C[mt][nt][2], C[mt][nt][3]);
        }
    }
}

// ---------------------------------------------------------------------------

extern "C" void kernel_launch(void* const* d_in, const int* in_sizes, int n_in,
                              void* d_out, int out_size) {
    const float* f1 = (const float*)d_in[0];   // [Z, 32]
    const float* f2 = (const float*)d_in[1];   // [Z, 32]
    const float* mx = (const float*)d_in[2];   // [64, 32, 32]
    float* out = (float*)d_out;                // [Z, 64]

    const int z_total = in_sizes[0] / N_I;     // 131072
    const int blocks = z_total / Z_CTA;        // 1024

    etp_pack_kernel<<<130, 256>>>(mx);         // 130*256 = 33280 incl. pad
    etp_mma_kernel<<<blocks, NTHREADS>>>(f1, f2, out);
}

// round 15
// speedup vs baseline: 1.5530x; 1.0401x over previous
#include <cuda_runtime.h>
#include <cuda_fp16.h>
#include <cstdint>

// ============================================================================
// out[z,k] = sum_{i,j} M[k,i,j] * f1[z,i] * f2[z,j]
// Dense fp16 warp-MMA GEMM (fp32 accum):  out = P @ W
//   P[z, i*32+j] = f1[z,i]*f2[z,j]  (HMUL2 of pre-converted fp16 operands)
//   W[i*32+j, k] = M[k,i,j]         (pre-packed fp16x2 fragment order, RN)
//
// R15 = R8 (best: m32n32, 256thr, 3 CTA/SM = 24 warps) with
//   #pragma unroll 2 on the ig loop: ptxas gets a 4-chunk scheduling window
//   to software-pipeline LDG/LDS/HMUL2 of chunk t+1 over the MMA burst of
//   chunk t, inside the 84-reg / 3-CTA envelope (manual pipelining in R14
//   cost 90 regs -> lost the 3rd CTA; ptxas rotates live ranges leaner).
// ============================================================================

#define N_I 32
#define N_J 32
#define N_K 64
#define Z_CTA 128              // 4 m-groups x 32 rows
#define NTHREADS 256           // 8 warps = 4 m-groups x 2 n-halves
#define N_CHUNKS 64            // K = 1024 / 16

// Packed W (uint32 = fp16x2), layout validated in R7/R8:
//   uint4 index = chunk*128 + nhalf*64 + pair*32 + lane
//   slot = ntl*2 + breg ; n = nhalf*32 + (pair*2+ntl)*8 + qr
//   i = chunk/2 ; j0 = (chunk&1)*16 + 2c + 8*breg ; value = {f16(j0), f16(j0+1)}
// +1 zero pad chunk so the last prefetch is legal.
__device__ uint32_t g_Wp[(N_CHUNKS + 1) * 512];   // 133 KB

// ---------------------------------------------------------------------------
__global__ void etp_pack_kernel(const float* __restrict__ Mx) {
    int idx = blockIdx.x * blockDim.x + threadIdx.x;   // 0..33279
    if (idx >= N_CHUNKS * 512) {
        if (idx < (N_CHUNKS + 1) * 512) g_Wp[idx] = 0u;
        return;
    }
    int chunk = idx >> 9;
    int rem   = idx & 511;
    int nhalf = rem >> 8;
    int r2    = rem & 255;
    int pair  = r2 >> 7;
    int r3    = r2 & 127;
    int lane  = r3 >> 2;
    int slot  = r3 & 3;
    int ntl   = slot >> 1;
    int breg  = slot & 1;
    int qr    = lane >> 2;
    int c     = lane & 3;
    int n     = nhalf * 32 + (pair * 2 + ntl) * 8 + qr;
    int i     = chunk >> 1;
    int j0    = ((chunk & 1) << 4) + 2 * c + 8 * breg;
    float v0 = Mx[n * (N_I * N_J) + i * N_J + j0];
    float v1 = Mx[n * (N_I * N_J) + i * N_J + j0 + 1];
    __half2 h = __floats2half2_rn(v0, v1);             // lo=v0, hi=v1
    g_Wp[idx] = *reinterpret_cast<uint32_t*>(&h);
}

// ---------------------------------------------------------------------------

#define HMUL2(d, x, y) \
    asm("mul.rn.f16x2 %0, %1, %2;" : "=r"(d) : "r"(x), "r"(y))

#define MMA_F16(cacc, a0, a1, a2, a3, b0, b1)                                 \
    asm volatile(                                                             \
        "mma.sync.aligned.m16n8k16.row.col.f32.f16.f16.f32 "                  \
        "{%0,%1,%2,%3}, {%4,%5,%6,%7}, {%8,%9}, {%0,%1,%2,%3};"               \
        : "+f"((cacc)[0]), "+f"((cacc)[1]), "+f"((cacc)[2]), "+f"((cacc)[3])  \
        : "r"(a0), "r"(a1), "r"(a2), "r"(a3), "r"(b0), "r"(b1))

__global__ void __launch_bounds__(NTHREADS, 3)
etp_mma_kernel(const float* __restrict__ F1,
               const float* __restrict__ F2,
               float* __restrict__ Out) {
    // f1 broadcast half2(v,v), stride 32, XOR-swizzled:
    //   word = row*32 + (col ^ ((row&7)<<2))
    __shared__ uint32_t f1h[Z_CTA * 32];                 // 16 KB

    const int tid    = threadIdx.x;
    const int warp   = tid >> 5;
    const int lane   = tid & 31;
    const int mgroup = warp >> 1;        // 0..3, 32 rows each
    const int nhalf  = warp & 1;         // n columns [nhalf*32, +32)
    const int qr     = lane >> 2;        // 0..7
    const int c      = lane & 3;         // 0..3

    const size_t zbase = (size_t)blockIdx.x * Z_CTA;

    // ---- stage f1 (broadcast half2, swizzled) ----
    {
        const float4* f1g = reinterpret_cast<const float4*>(F1 + zbase * N_I);
#pragma unroll
        for (int t = 0; t < 4; t++) {
            int i4 = tid + t * NTHREADS;          // 0..1023
            int row = i4 >> 3, cg = i4 & 7;
            float4 v1 = __ldg(f1g + i4);
            __half2 h0 = __half2half2(__float2half_rn(v1.x));
            __half2 h1 = __half2half2(__float2half_rn(v1.y));
            __half2 h2 = __half2half2(__float2half_rn(v1.z));
            __half2 h3 = __half2half2(__float2half_rn(v1.w));
            uint4 pk;
            pk.x = *reinterpret_cast<uint32_t*>(&h0);
            pk.y = *reinterpret_cast<uint32_t*>(&h1);
            pk.z = *reinterpret_cast<uint32_t*>(&h2);
            pk.w = *reinterpret_cast<uint32_t*>(&h3);
            int col = (cg * 4) ^ ((row & 7) << 2);       // keeps low 2 bits
            *reinterpret_cast<uint4*>(&f1h[row * 32 + col]) = pk;
        }
    }

    const int r0 = mgroup * 32 + qr;     // rows r0, r0+8, r0+16, r0+24

    // ---- f2 pair regs direct from gmem: s2 = jh*2+breg -> j0 = jh*16+breg*8+2c
    uint32_t f2h[4][4];
#pragma unroll
    for (int rr = 0; rr < 4; rr++) {
        const float* fr = F2 + (zbase + r0 + rr * 8) * N_J;
#pragma unroll
        for (int s2 = 0; s2 < 4; s2++) {
            int jh = s2 >> 1, breg = s2 & 1;
            int j0 = jh * 16 + breg * 8 + 2 * c;
            float2 v = *reinterpret_cast<const float2*>(fr + j0);
            __half2 h = __floats2half2_rn(v.x, v.y);
            f2h[rr][s2] = *reinterpret_cast<uint32_t*>(&h);
        }
    }

    float C[2][4][4];                    // [mtile][ntile][quad]
#pragma unroll
    for (int mt = 0; mt < 2; mt++)
#pragma unroll
        for (int nt = 0; nt < 4; nt++)
#pragma unroll
            for (int q = 0; q < 4; q++) C[mt][nt][q] = 0.0f;

    __syncthreads();                     // f1h visible

    const int sw = qr << 2;              // f1 swizzle term (row&7 == qr)

    // ---- B stream: 2x lane-contiguous LDG.128 per chunk, 1-chunk lookahead
    const uint4* wq = reinterpret_cast<const uint4*>(g_Wp)
                      + nhalf * 64 + lane;
    uint4 bA = __ldg(wq);                // pair 0: n-tiles 0,1
    uint4 bB = __ldg(wq + 32);           // pair 1: n-tiles 2,3

#pragma unroll 2
    for (int ig = 0; ig < N_I; ig++) {
        uint32_t f1v[4];
#pragma unroll
        for (int rr = 0; rr < 4; rr++)
            f1v[rr] = f1h[(r0 + rr * 8) * 32 + (ig ^ sw)];

#pragma unroll
        for (int jh = 0; jh < 2; jh++) {
            const uint4 b0 = bA, b1 = bB;

            wq += 128;                   // next chunk (pad keeps last legal)
            bA = __ldg(wq);
            bB = __ldg(wq + 32);

            // A fragments: one HMUL2 each
            uint32_t a[2][4];
#pragma unroll
            for (int mt = 0; mt < 2; mt++) {
                HMUL2(a[mt][0], f1v[2 * mt],     f2h[2 * mt][jh * 2 + 0]);
                HMUL2(a[mt][1], f1v[2 * mt + 1], f2h[2 * mt + 1][jh * 2 + 0]);
                HMUL2(a[mt][2], f1v[2 * mt],     f2h[2 * mt][jh * 2 + 1]);
                HMUL2(a[mt][3], f1v[2 * mt + 1], f2h[2 * mt + 1][jh * 2 + 1]);
            }

            // 8 MMAs (2 mtiles x 4 ntiles), K=16 each
#pragma unroll
            for (int mt = 0; mt < 2; mt++) {
                MMA_F16(C[mt][0], a[mt][0], a[mt][1], a[mt][2], a[mt][3], b0.x, b0.y);
                MMA_F16(C[mt][1], a[mt][0], a[mt][1], a[mt][2], a[mt][3], b0.z, b0.w);
                MMA_F16(C[mt][2], a[mt][0], a[mt][1], a[mt][2], a[mt][3], b1.x, b1.y);
                MMA_F16(C[mt][3], a[mt][0], a[mt][1], a[mt][2], a[mt][3], b1.z, b1.w);
            }
        }
    }

    // ---- epilogue ----
#pragma unroll
    for (int mt = 0; mt < 2; mt++) {
        const size_t z0 = zbase + r0 + mt * 16;
        const size_t z1 = z0 + 8;
#pragma unroll
        for (int nt = 0; nt < 4; nt++) {
            const int col = nhalf * 32 + nt * 8 + 2 * c;
            *reinterpret_cast<float2*>(Out + z0 * N_K + col) =
                make_float2(C[mt][nt][0], C[mt][nt][1]);
            *reinterpret_cast<float2*>(Out + z1 * N_K + col) =
                make_float2(C[mt][nt][2], C[mt][nt][3]);
        }
    }
}

// ---------------------------------------------------------------------------

extern "C" void kernel_launch(void* const* d_in, const int* in_sizes, int n_in,
                              void* d_out, int out_size) {
    const float* f1 = (const float*)d_in[0];   // [Z, 32]
    const float* f2 = (const float*)d_in[1];   // [Z, 32]
    const float* mx = (const float*)d_in[2];   // [64, 32, 32]
    float* out = (float*)d_out;                // [Z, 64]

    const int z_total = in_sizes[0] / N_I;     // 131072
    const int blocks = z_total / Z_CTA;        // 1024

    etp_pack_kernel<<<130, 256>>>(mx);         // 130*256 = 33280 incl. pad
    etp_mma_kernel<<<blocks, NTHREADS>>>(f1, f2, out);
}